// round 7
// baseline (speedup 1.0000x reference)
#include <cuda_runtime.h>

// TSM temporal shift: x (128, 96, 56, 56) f32, N_FRAME=8, fold=32.
//   c in [0,32):  out[b,t] = x[b,t+1]  (0 at t=7)
//   c in [32,64): out[b,t] = x[b,t-1]  (0 at t=0)
//   c in [64,96): copy
// R4: schedule-shaping probe at the HBM roofline (~7.2 TB/s effective,
// ~90% of spec). TPB=512, V=7 (exact: 25088 = 7*512*7), grid (7,3,128),
// load/store software-interleave so the R/W mix is steady.

static constexpr int HW4     = (56 * 56) / 4;   // 784 float4 per channel plane
static constexpr int G4      = 32 * HW4;        // 25088 float4 per group per bt
static constexpr int PER_BT4 = 3 * G4;          // 75264 float4 per bt slice
static constexpr int V       = 7;               // float4 per thread
static constexpr int TPB     = 512;
static constexpr int BLK_X   = G4 / (V * TPB);  // 7, exact

__global__ __launch_bounds__(TPB) void tsm_kernel(const float4* __restrict__ in,
                                                  float4* __restrict__ out) {
    const int g  = blockIdx.y;       // channel group: 0 = t+1, 1 = t-1, 2 = copy
    const int bt = blockIdx.z;
    const int t  = bt & 7;           // frame within clip of 8

    const int  dt    = (g == 0) ? 1 : ((g == 1) ? -1 : 0);
    const bool valid = (g == 2) || ((g == 0) ? (t < 7) : (t > 0));

    const int chunk = g * G4 + blockIdx.x * (V * TPB) + threadIdx.x;
    const float4* src = in  + (bt + dt) * PER_BT4 + chunk;
    float4*       dst = out + bt * PER_BT4 + chunk;

    if (valid) {
        float4 v[V];
        // Front-batch a window of loads, then stream store-k / remaining loads
        // interleaved so reads and writes mix steadily at the controller.
        #pragma unroll
        for (int k = 0; k < 4; k++) v[k] = __ldcs(src + k * TPB);
        #pragma unroll
        for (int k = 4; k < V; k++) {
            v[k] = __ldcs(src + k * TPB);
            __stcs(dst + (k - 4) * TPB, v[k - 4]);
        }
        #pragma unroll
        for (int k = V - 4; k < V; k++) __stcs(dst + k * TPB, v[k]);
    } else {
        const float4 z = make_float4(0.f, 0.f, 0.f, 0.f);
        #pragma unroll
        for (int k = 0; k < V; k++) __stcs(dst + k * TPB, z);
    }
}

extern "C" void kernel_launch(void* const* d_in, const int* in_sizes, int n_in,
                              void* d_out, int out_size) {
    const float4* in  = (const float4*)d_in[0];
    float4*       out = (float4*)d_out;

    dim3 grid(BLK_X, 3, 128);   // (7, 3, 128) = 2688 blocks, exact cover
    tsm_kernel<<<grid, TPB>>>(in, out);
}

// round 12
// speedup vs baseline: 1.0221x; 1.0221x over previous
#include <cuda_runtime.h>

// TSM temporal shift: x (128, 96, 56, 56) f32, N_FRAME=8, fold=32.
//   c in [0,32):  out[b,t] = x[b,t+1]  (0 at t=7)
//   c in [32,64): out[b,t] = x[b,t-1]  (0 at t=0)
//   c in [64,96): copy
// R5: fine-grained CTA probe at the HBM copy-roofline. Block-uniform
// decomposition (group -> blockIdx.y, bt -> blockIdx.z), TPB=128, V=7
// (exact: 25088 = 28 * 128 * 7), grid (28,3,128) = 10752 small CTAs for
// finer, steadier R/W interleave at the memory controllers.
// Demand traffic is irreducible at 289 MB; ~7.2 TB/s delivered already.

static constexpr int HW4     = (56 * 56) / 4;   // 784 float4 per channel plane
static constexpr int G4      = 32 * HW4;        // 25088 float4 per group per bt
static constexpr int PER_BT4 = 3 * G4;          // 75264 float4 per bt slice
static constexpr int V       = 7;               // float4 per thread
static constexpr int TPB     = 128;
static constexpr int BLK_X   = G4 / (V * TPB);  // 28, exact

__global__ __launch_bounds__(TPB) void tsm_kernel(const float4* __restrict__ in,
                                                  float4* __restrict__ out) {
    const int g  = blockIdx.y;       // channel group: 0 = t+1, 1 = t-1, 2 = copy
    const int bt = blockIdx.z;
    const int t  = bt & 7;           // frame within clip of 8

    // Block-uniform source shift and validity.
    const int  dt    = (g == 0) ? 1 : ((g == 1) ? -1 : 0);
    const bool valid = (g == 2) || ((g == 0) ? (t < 7) : (t > 0));

    const int chunk = g * G4 + blockIdx.x * (V * TPB) + threadIdx.x;
    const float4* src = in  + (bt + dt) * PER_BT4 + chunk;
    float4*       dst = out + bt * PER_BT4 + chunk;

    float4 v[V];
    if (valid) {
        // Front-batched loads: 7 independent LDG.128 in flight per thread.
        #pragma unroll
        for (int k = 0; k < V; k++) v[k] = __ldcs(src + k * TPB);
    } else {
        #pragma unroll
        for (int k = 0; k < V; k++) v[k] = make_float4(0.f, 0.f, 0.f, 0.f);
    }

    #pragma unroll
    for (int k = 0; k < V; k++) __stcs(dst + k * TPB, v[k]);
}

extern "C" void kernel_launch(void* const* d_in, const int* in_sizes, int n_in,
                              void* d_out, int out_size) {
    const float4* in  = (const float4*)d_in[0];
    float4*       out = (float4*)d_out;

    dim3 grid(BLK_X, 3, 128);   // (28, 3, 128) = 10752 blocks, exact cover
    tsm_kernel<<<grid, TPB>>>(in, out);
}